// round 17
// baseline (speedup 1.0000x reference)
#include <cuda_runtime.h>

// Problem constants (shapes are fixed for this problem instance)
#define NMAX   16000
#define EMAX   48000
#define FMAX   32000
#define NGRAPH 32
#define NBUMP  32
#define NDIR   64
#define NHID   256
#define NCLS   10

#define SORT_BLOCKS  128
#define SORT_THREADS 256

#define ECC_L     48                 // items per thread-run
#define ECC_ITEMS 192                // 4 runs * 48 items per block
#define ACC_PAD   33                 // bank-conflict-free column stride

// Scratch (device globals: allocation-free per harness rules)
static __device__ float g_nh[NMAX * NDIR];              // node heights [N][64]
static __device__ float g_diff[NGRAPH * NDIR * NBUMP];  // delta accum, layout [g][d][b]
static __device__ int   g_bcnt[SORT_BLOCKS * 64];       // per-block bucket counts
static __device__ int   g_boff[SORT_BLOCKS * 64];       // per-block bucket offsets
static __device__ unsigned g_perm[EMAX + FMAX];         // packed (g<<20)|item_idx

__device__ __forceinline__ float rcpa(float x) {
    float r;
    asm("rcp.approx.f32 %0, %1;" : "=f"(r) : "f"(x));
    return r;
}

__device__ __forceinline__ void red4(float* p, float a, float b, float c, float d) {
    asm volatile("red.global.add.v4.f32 [%0], {%1,%2,%3,%4};"
                 :: "l"(p), "f"(a), "f"(b), "f"(c), "f"(d) : "memory");
}

// ---------- A: fused init (nh | per-block count | zero diff | zero logits) ----------
__global__ void k_init(const float* __restrict__ x, const float* __restrict__ nw,
                       const float* __restrict__ v, const int* __restrict__ ei,
                       const int* __restrict__ fc, const int* __restrict__ bid,
                       float* __restrict__ out, int N, int E, int F, int nhB) {
    __shared__ int h[64];
    int blk = blockIdx.x, t = threadIdx.x;
    if (blk < nhB) {                               // node heights
        int idx = blk * 256 + t;
        if (idx < N * NDIR) {
            int n = idx >> 6, d = idx & 63;
            g_nh[idx] = nw[n] * (x[3 * n]     * v[d] +
                                 x[3 * n + 1] * v[NDIR + d] +
                                 x[3 * n + 2] * v[2 * NDIR + d]);
        }
    } else if (blk < nhB + SORT_BLOCKS) {          // histogram by graph
        int cb = blk - nhB;
        if (t < 64) h[t] = 0;
        __syncthreads();
        for (int i = cb * SORT_THREADS + t; i < E + F; i += SORT_BLOCKS * SORT_THREADS) {
            int bkt = (i < E) ? bid[ei[i]] : (32 + bid[fc[i - E]]);
            atomicAdd(&h[bkt], 1);
        }
        __syncthreads();
        if (t < 64) g_bcnt[cb * 64 + t] = h[t];
    } else if (blk < nhB + SORT_BLOCKS + 32) {     // zero g_diff
        int zb = blk - nhB - SORT_BLOCKS;
        float4 z = {0.f, 0.f, 0.f, 0.f};
        float4* p = (float4*)(g_diff + zb * 2048);
        p[t * 2] = z; p[t * 2 + 1] = z;
    } else {                                       // zero ALL logits (320 > 256!)
        for (int i = t; i < NGRAPH * NCLS; i += 256) out[i] = 0.f;
    }
}

// ---------- B: offsets (smem-staged scan; edge buckets start 0, face at E) ----------
__global__ void k_offsets(int E) {
    __shared__ int sc[SORT_BLOCKS * 64];
    __shared__ int tot[64], base[64];
    int t = threadIdx.x;
    for (int i = t; i < SORT_BLOCKS * 64; i += 256) sc[i] = g_bcnt[i];
    __syncthreads();
    if (t < 64) {
        int a0 = 0, a1 = 0, a2 = 0, a3 = 0;
        for (int k = 0; k < SORT_BLOCKS; k += 4) {
            a0 += sc[k * 64 + t];       a1 += sc[(k + 1) * 64 + t];
            a2 += sc[(k + 2) * 64 + t]; a3 += sc[(k + 3) * 64 + t];
        }
        tot[t] = a0 + a1 + a2 + a3;
    }
    __syncthreads();
    if (t == 0) {
        int a = 0;
        for (int k = 0; k < 32; ++k)  { base[k] = a; a += tot[k]; }
        a = E;
        for (int k = 32; k < 64; ++k) { base[k] = a; a += tot[k]; }
    }
    __syncthreads();
    if (t < 64) {
        int run = base[t];
        for (int k = 0; k < SORT_BLOCKS; ++k) {
            g_boff[k * 64 + t] = run;
            run += sc[k * 64 + t];
        }
    }
}

// ---------- C: scatter with per-block smem cursors ----------
__global__ void k_scatter(const int* __restrict__ ei, const int* __restrict__ fc,
                          const int* __restrict__ bid, int E, int F) {
    __shared__ int cur[64];
    if (threadIdx.x < 64) cur[threadIdx.x] = g_boff[blockIdx.x * 64 + threadIdx.x];
    __syncthreads();
    for (int i = blockIdx.x * SORT_THREADS + threadIdx.x; i < E + F;
         i += SORT_BLOCKS * SORT_THREADS) {
        int g, idx, bkt;
        if (i < E) { idx = i;     g = bid[ei[i]];     bkt = g; }
        else       { idx = i - E; g = bid[fc[i - E]]; bkt = 32 + g; }
        int pos = atomicAdd(&cur[bkt], 1);
        g_perm[pos] = ((unsigned)g << 20) | (unsigned)idx;
    }
}

// ---------- D: unified ECC with per-thread smem accumulators ----------
__device__ __forceinline__ void flushacc(const float* a, int g, int d) {
    float* p = &g_diff[(g << 11) + (d << 5)];
    #pragma unroll
    for (int q = 0; q < 8; ++q)
        red4(p + q * 4, a[q * 4], a[q * 4 + 1], a[q * 4 + 2], a[q * 4 + 3]);
}

// Items: [0,N) nodes (+), [N,N+E) edges (-) via perm, [N+E,N+E+F) faces (+) via perm.
// Thread = (dir d = tid&63, run c = tid>>6). Private 32-bin smem column
// (pad 33 -> conflict-free); flush to g_diff with v4 REDs on graph change/end.
__global__ void k_ecc(const float* __restrict__ ew, const float* __restrict__ fw,
                      const int* __restrict__ ei, const int* __restrict__ fc,
                      const int* __restrict__ bid, int N, int E, int F) {
    __shared__ float acc[256 * ACC_PAD];
    int t = threadIdx.x;
    int d = t & 63;
    float* a = &acc[t * ACC_PAD];
    #pragma unroll
    for (int b = 0; b < 32; ++b) a[b] = 0.0f;

    int M = N + E + F;
    int i0 = blockIdx.x * ECC_ITEMS + (t >> 6) * ECC_L;
    int i1 = min(i0 + ECC_L, M);
    int curg = -1;

    const float Bc    = 6.4516129032f;      // 200/31
    const float invB  = 0.155f;             // 31/200
    const float T     = 10.0f;
    const float invEB = 0.00157827970f;     // exp(-200/31)

    for (int i = i0; i < i1; ++i) {
        int g; float h, sgn;
        if (i < N) {                         // node
            g = bid[i];
            h = g_nh[(i << 6) + d];
            sgn = 1.0f;
        } else {
            unsigned p = g_perm[i - N];
            g = p >> 20;
            int e = p & 0xFFFFF;
            if (i < N + E) {                 // edge
                int u = ei[e], w = ei[E + e];
                h = fmaxf(g_nh[(u << 6) + d], g_nh[(w << 6) + d]) * ew[e];
                sgn = -1.0f;
            } else {                         // face
                int u = fc[e], w = fc[F + e], y = fc[2 * F + e];
                h = fmaxf(fmaxf(g_nh[(u << 6) + d], g_nh[(w << 6) + d]),
                          g_nh[(y << 6) + d]) * fw[e];
                sgn = 1.0f;
            }
        }
        if (g != curg) {                     // warp-uniform branch (same item)
            if (curg >= 0) {
                flushacc(a, curg, d);
                #pragma unroll
                for (int b = 0; b < 32; ++b) a[b] = 0.0f;
            }
            curg = g;
        }
        // monotone sigmoid staircase as difference array, band |z| < T
        float A = fmaf(h, -100.0f, -100.0f);   // z(b) = A + b*Bc
        if (A < -T - 31.0f * Bc) continue;     // whole curve ~0
        int b0 = (int)ceilf((-T - A) * invB);
        b0 = max(b0, 0); b0 = min(b0, 31);
        int b1 = (int)floorf((T - A) * invB);
        b1 = min(b1, 31);
        float q = __expf(-fmaf((float)b0, Bc, A));
        float sprev = 0.0f;
        for (int b = b0; b <= b1; ++b) {
            float s = rcpa(1.0f + q);          // sigmoid = 1/(1+e^-z)
            a[b] += (s - sprev) * sgn;
            sprev = s;
            q *= invEB;
        }
        int bx = max(b1 + 1, 0);               // closing step to all-ones tail
        if (bx <= 31) a[bx] += (1.0f - sprev) * sgn;
    }
    if (curg >= 0) flushacc(a, curg, d);
}

// ---------- E: fused prefix + hidden + logits ----------
// Block = (g = blockIdx>>3, chunk c = blockIdx&7 of 32 hidden units).
// 1) load g_diff[g] slab, prefix-sum over b into s_flat[b*64+d]
// 2) c==0 writes flat to d_out
// 3) 8 warps x 4 hids: 2048-dot vs W1, relu -> s_hid[32]
// 4) partial logits for this chunk -> atomicAdd into out (zeroed in k_init)
__global__ void k_mlp(const float* __restrict__ W1, const float* __restrict__ b1,
                      const float* __restrict__ W2, const float* __restrict__ b2,
                      float* __restrict__ out) {
    __shared__ __align__(16) float s_flat[2048];
    __shared__ float s_tmp[64 * 33];
    __shared__ float s_hid[32];
    __shared__ float s_w2[NCLS * 32];
    int t = threadIdx.x;
    int g = blockIdx.x >> 3, c = blockIdx.x & 7;

    // load [d][b] slab with padded smem layout (conflict-free column scan)
    for (int k = t; k < 2048; k += 256)
        s_tmp[(k >> 5) * 33 + (k & 31)] = g_diff[(g << 11) + k];
    __syncthreads();
    if (t < 64) {                            // serial prefix over b for dir t
        float s = 0.0f;
        #pragma unroll
        for (int b = 0; b < 32; ++b) {
            s += s_tmp[t * 33 + b];
            s_flat[b * 64 + t] = s;
        }
    }
    __syncthreads();

    float* flat = out + NGRAPH * NCLS;
    if (c == 0) {                            // one chunk per g emits flat output
        float4* dst = (float4*)(flat + (g << 11));
        const float4* src = (const float4*)s_flat;
        for (int k = t; k < 512; k += 256) dst[k] = src[k];
    }

    // hidden dots: warp w handles hids c*32 + w*4 .. +3
    int w = t >> 5, lane = t & 31;
    int h0 = c * 32 + w * 4;
    const float4* sf4 = (const float4*)s_flat;
    const float4* W14 = (const float4*)W1;
    float a0 = 0.f, a1 = 0.f, a2 = 0.f, a3 = 0.f;
    #pragma unroll
    for (int j = 0; j < 16; ++j) {
        float4 fa = sf4[lane + 32 * j];
        float4 w0 = W14[(h0 + 0) * 512 + lane + 32 * j];
        float4 w1 = W14[(h0 + 1) * 512 + lane + 32 * j];
        float4 w2v = W14[(h0 + 2) * 512 + lane + 32 * j];
        float4 w3 = W14[(h0 + 3) * 512 + lane + 32 * j];
        a0 += fa.x * w0.x + fa.y * w0.y + fa.z * w0.z + fa.w * w0.w;
        a1 += fa.x * w1.x + fa.y * w1.y + fa.z * w1.z + fa.w * w1.w;
        a2 += fa.x * w2v.x + fa.y * w2v.y + fa.z * w2v.z + fa.w * w2v.w;
        a3 += fa.x * w3.x + fa.y * w3.y + fa.z * w3.z + fa.w * w3.w;
    }
    #pragma unroll
    for (int o = 16; o; o >>= 1) {
        a0 += __shfl_xor_sync(0xffffffffu, a0, o);
        a1 += __shfl_xor_sync(0xffffffffu, a1, o);
        a2 += __shfl_xor_sync(0xffffffffu, a2, o);
        a3 += __shfl_xor_sync(0xffffffffu, a3, o);
    }
    if (lane == 0) {
        s_hid[w * 4 + 0] = fmaxf(a0 + b1[h0 + 0], 0.f);
        s_hid[w * 4 + 1] = fmaxf(a1 + b1[h0 + 1], 0.f);
        s_hid[w * 4 + 2] = fmaxf(a2 + b1[h0 + 2], 0.f);
        s_hid[w * 4 + 3] = fmaxf(a3 + b1[h0 + 3], 0.f);
    }

    // stage this chunk's W2 columns
    for (int u = t; u < NCLS * 32; u += 256)
        s_w2[u] = W2[(u >> 5) * NHID + c * 32 + (u & 31)];
    __syncthreads();

    if (t < NCLS) {                          // partial logits for this chunk
        float s = (c == 0) ? b2[t] : 0.f;
        #pragma unroll
        for (int k = 0; k < 32; ++k) s += s_hid[k] * s_w2[t * 32 + k];
        atomicAdd(&out[g * NCLS + t], s);
    }
}

extern "C" void kernel_launch(void* const* d_in, const int* in_sizes, int n_in,
                              void* d_out, int out_size) {
    const float* x  = (const float*)d_in[0];
    const float* nw = (const float*)d_in[1];
    const float* ew = (const float*)d_in[2];
    const float* fw = (const float*)d_in[3];
    const float* v  = (const float*)d_in[4];
    const float* W1 = (const float*)d_in[5];
    const float* b1 = (const float*)d_in[6];
    const float* W2 = (const float*)d_in[7];
    const float* b2 = (const float*)d_in[8];
    const int*   ei = (const int*)d_in[9];   // edge_index [2,E] (int32)
    const int*   fc = (const int*)d_in[10];  // face [3,F]
    const int*   bid= (const int*)d_in[11];  // batch_ids [N]

    int N = in_sizes[1];   // node_weights count
    int E = in_sizes[2];   // edge_weights count
    int F = in_sizes[3];   // face_weights count
    int M = N + E + F;

    float* out = (float*)d_out;            // [0,320): logits; [320,+65536): flat

    int nhB = (N * NDIR + 255) / 256;
    k_init<<<nhB + SORT_BLOCKS + 32 + 1, 256>>>(x, nw, v, ei, fc, bid, out, N, E, F, nhB);
    k_offsets<<<1, 256>>>(E);
    k_scatter<<<SORT_BLOCKS, SORT_THREADS>>>(ei, fc, bid, E, F);
    k_ecc<<<(M + ECC_ITEMS - 1) / ECC_ITEMS, 256>>>(ew, fw, ei, fc, bid, N, E, F);
    k_mlp<<<NGRAPH * 8, 256>>>(W1, b1, W2, b2, out);
}